// round 2
// baseline (speedup 1.0000x reference)
#include <cuda_runtime.h>
#include <cuda_bf16.h>
#include <math.h>

#define S_ 128
#define B_ 64
#define V_ 10000
#define E_ 256
#define H_ 512
#define SB_ (S_*B_)     // 8192
#define NB 128          // persistent CTAs in scan kernel

typedef unsigned long long u64;

// ---------------- packed f32x2 helpers (Blackwell FFMA2) ----------------
__device__ __forceinline__ void fma2(u64& d, u64 a, u64 b) {
    asm("fma.rn.f32x2 %0, %1, %2, %0;" : "+l"(d) : "l"(a), "l"(b));
}
__device__ __forceinline__ float2 unpack2(u64 v) {
    float2 f;
    asm("mov.b64 {%0, %1}, %2;" : "=f"(f.x), "=f"(f.y) : "l"(v));
    return f;
}

// ---------------- device scratch (static allocations are allowed) ----------------
__device__ float g_ax[3][SB_*H_];     // layer0 x-contrib + bias, gates r,z,h  (48 MB)
__device__ float g_H1[SB_*H_];        // h1 for every step (16 MB)
__device__ float g_h0[2][B_*H_];      // ping-pong layer0 state
__device__ float g_h1[2][B_*H_];      // ping-pong layer1 state
__device__ float g_r0[B_*H_], g_z0[B_*H_], g_r1[B_*H_], g_z1[B_*H_];
__device__ unsigned g_flag[NB];       // per-CTA barrier flags (reset each launch)

__global__ void reset_kernel() {
    int i = threadIdx.x;
    if (i < NB) g_flag[i] = 0;
}

// Flag-array grid barrier. Per-CTA release-store of its generation, 128
// parallel acquire-pollers. All NB CTAs co-resident (NB=128 <= 148 SMs,
// 1 CTA/SM by smem). Flags reset to 0 in stream order before the scan
// kernel each launch, so graph replays are safe.
__device__ __forceinline__ void gsync(unsigned* gen) {
    (*gen)++;
    unsigned g = *gen;
    __syncthreads();
    if (threadIdx.x == 0) {
        asm volatile("st.release.gpu.global.u32 [%0], %1;"
                     :: "l"(&g_flag[blockIdx.x]), "r"(g) : "memory");
    }
    if (threadIdx.x < NB) {
        unsigned v;
        do {
            asm volatile("ld.acquire.gpu.global.u32 %0, [%1];"
                         : "=r"(v) : "l"(&g_flag[threadIdx.x]) : "memory");
        } while (v < g);
    }
    __syncthreads();
}

__device__ __forceinline__ float sigmoidf_(float x) { return 1.f / (1.f + expf(-x)); }

// ============================================================================
// Phase 1: ax_g[t,b,:] = emb[tok[t,b]] @ Wx_g.T + b_g   (g = r,z,h of layer 0)
// M=8192, N=512, K=256. 64x64 tile, 4x4 micro, K-chunk 32.
// ============================================================================
__global__ __launch_bounds__(256) void phase1_kernel(
    const int*   __restrict__ inputs, const float* __restrict__ emb,
    const float* __restrict__ W_r0, const float* __restrict__ b_r0,
    const float* __restrict__ W_z0, const float* __restrict__ b_z0,
    const float* __restrict__ W_h0, const float* __restrict__ b_h0)
{
    __shared__ float As[32*68];
    __shared__ float Bs[32*68];
    __shared__ int   tok[64];
    int tid = threadIdx.x;
    int g = blockIdx.z;
    const float* W  = (g == 0) ? W_r0 : (g == 1) ? W_z0 : W_h0;
    const float* bg = (g == 0) ? b_r0 : (g == 1) ? b_z0 : b_h0;
    int m0 = blockIdx.y * 64;
    int n0 = blockIdx.x * 64;
    if (tid < 64) tok[tid] = inputs[m0 + tid];
    __syncthreads();

    int tx = tid & 15, ty = tid >> 4;   // tx -> n, ty -> m
    float acc[4][4];
#pragma unroll
    for (int i = 0; i < 4; i++)
#pragma unroll
        for (int j = 0; j < 4; j++) acc[i][j] = 0.f;

    for (int k0 = 0; k0 < E_; k0 += 32) {
        __syncthreads();
#pragma unroll
        for (int r = 0; r < 8; r++) {
            int idx = tid + r * 256;
            int row = idx >> 5, kk = idx & 31;
            As[kk*68 + row] = emb[tok[row] * E_ + k0 + kk];
            Bs[kk*68 + row] = W[(n0 + row) * (H_ + E_) + H_ + k0 + kk];
        }
        __syncthreads();
#pragma unroll
        for (int kk = 0; kk < 32; kk++) {
            float4 a = *reinterpret_cast<const float4*>(As + kk*68 + ty*4);
            float4 b = *reinterpret_cast<const float4*>(Bs + kk*68 + tx*4);
            acc[0][0] += a.x*b.x; acc[0][1] += a.x*b.y; acc[0][2] += a.x*b.z; acc[0][3] += a.x*b.w;
            acc[1][0] += a.y*b.x; acc[1][1] += a.y*b.y; acc[1][2] += a.y*b.z; acc[1][3] += a.y*b.w;
            acc[2][0] += a.z*b.x; acc[2][1] += a.z*b.y; acc[2][2] += a.z*b.z; acc[2][3] += a.z*b.w;
            acc[3][0] += a.w*b.x; acc[3][1] += a.w*b.y; acc[3][2] += a.w*b.z; acc[3][3] += a.w*b.w;
        }
    }
    float* outp = g_ax[g];
#pragma unroll
    for (int i = 0; i < 4; i++) {
        int m = m0 + ty*4 + i;
#pragma unroll
        for (int j = 0; j < 4; j++) {
            int n = n0 + tx*4 + j;
            outp[m * H_ + n] = acc[i][j] + bg[n];
        }
    }
}

// ============================================================================
// Phase 2: persistent scan kernel. 128 CTAs x 256 threads.
// All recurrent weights resident in smem (~72 KB/CTA), weight-stationary.
// Per step: 4 GEMM stages with grid barriers between them. FFMA2 inner loop.
// ============================================================================
constexpr int W_A = 8 * 512;     // r0/z0 h-part rows (8 cols/CTA)
constexpr int W_B = 4 * 512;     // h~0 h-part rows (4 cols/CTA)
constexpr int W_C = 8 * 1024;    // r1/z1 full rows (8 cols/CTA)
constexpr int W_D = 4 * 1024;    // h~1 full rows (4 cols/CTA)
constexpr int TILE_F = 64 * 68;  // input tile [64 b][64 k], stride 68
constexpr int SCAN_SMEM_BYTES = (W_A + W_B + W_C + W_D + TILE_F) * 4;  // 91136

template<int NCOLS, int K, class LoadF>
__device__ __forceinline__ void gemm_stage(const float* __restrict__ w, float* tile,
                                           LoadF load, int tid, float& acc0, float& acc1)
{
    int b = tid & 63, js = tid >> 6;
    u64 p0 = 0ull, p1 = 0ull;   // bit pattern 0 == (0.f, 0.f)
    for (int k0 = 0; k0 < K; k0 += 64) {
        __syncthreads();
#pragma unroll
        for (int r = 0; r < 16; r++) {
            int idx = tid + r * 256;
            int bb = idx >> 6, kk = idx & 63;
            tile[bb*68 + kk] = load(bb, k0 + kk);
        }
        __syncthreads();
        const ulonglong2* a2  = reinterpret_cast<const ulonglong2*>(tile + b*68);
        const ulonglong2* w0p = reinterpret_cast<const ulonglong2*>(w + js*K + k0);
        const ulonglong2* w1p = reinterpret_cast<const ulonglong2*>(w + (js+4)*K + k0);
#pragma unroll
        for (int q = 0; q < 16; q++) {
            ulonglong2 a = a2[q];
            ulonglong2 x = w0p[q];
            fma2(p0, a.x, x.x);
            fma2(p0, a.y, x.y);
            if (NCOLS == 8) {
                ulonglong2 y = w1p[q];
                fma2(p1, a.x, y.x);
                fma2(p1, a.y, y.y);
            }
        }
    }
    float2 f0 = unpack2(p0);
    acc0 = f0.x + f0.y;
    if (NCOLS == 8) {
        float2 f1 = unpack2(p1);
        acc1 = f1.x + f1.y;
    } else {
        acc1 = 0.f;
    }
}

__global__ __launch_bounds__(256, 1) void scan_kernel(
    const float* __restrict__ hidden_in,
    const float* __restrict__ W_r0, const float* __restrict__ W_z0, const float* __restrict__ W_h0,
    const float* __restrict__ W_r1, const float* __restrict__ b_r1,
    const float* __restrict__ W_z1, const float* __restrict__ b_z1,
    const float* __restrict__ W_h1, const float* __restrict__ b_h1,
    float* __restrict__ d_out, int out_size)
{
    extern __shared__ float smem[];
    float* wA   = smem;
    float* wB   = wA + W_A;
    float* wC   = wB + W_B;
    float* wD   = wC + W_C;
    float* tile = wD + W_D;
    int tid = threadIdx.x;
    int c = blockIdx.x;

    // ---- preload this CTA's weight rows into smem ----
    for (int idx = tid; idx < W_A; idx += 256) {          // 8 cols, K=512 (h part)
        int i = idx >> 9, k = idx & 511;
        int v = c*8 + i;
        wA[idx] = (v < H_) ? W_r0[v*(H_+E_) + k] : W_z0[(v-H_)*(H_+E_) + k];
    }
    for (int idx = tid; idx < W_B; idx += 256) {          // 4 cols, K=512
        int i = idx >> 9, k = idx & 511;
        wB[idx] = W_h0[(c*4 + i)*(H_+E_) + k];
    }
    for (int idx = tid; idx < W_C; idx += 256) {          // 8 cols, K=1024
        int i = idx >> 10, k = idx & 1023;
        int v = c*8 + i;
        wC[idx] = (v < H_) ? W_r1[v*(2*H_) + k] : W_z1[(v-H_)*(2*H_) + k];
    }
    for (int idx = tid; idx < W_D; idx += 256) {          // 4 cols, K=1024
        int i = idx >> 10, k = idx & 1023;
        wD[idx] = W_h1[(c*4 + i)*(2*H_) + k];
    }
    // ---- init states from the provided hidden input ([L,B,H]) ----
    for (int idx = c*256 + tid; idx < B_*H_; idx += NB*256) {
        g_h0[0][idx] = hidden_in[idx];
        g_h1[0][idx] = hidden_in[B_*H_ + idx];
    }
    unsigned gen = 0;
    gsync(&gen);

    int b = tid & 63, js = tid >> 6;

    for (int t = 0; t < S_; t++) {
        int p = t & 1;
        const float* h0p = g_h0[p];
        const float* h1p = g_h1[p];
        float* h0n = g_h0[p ^ 1];
        float* h1n = g_h1[p ^ 1];
        const float* axr = g_ax[0] + t * (B_*H_);
        const float* axz = g_ax[1] + t * (B_*H_);
        const float* axh = g_ax[2] + t * (B_*H_);

        // ---- Stage A: r0, z0 = sigmoid(h0 @ Wh.T + ax) ----
        {
            float a0, a1;
            gemm_stage<8, H_>(wA, tile,
                [&](int bb, int k) { return h0p[bb*H_ + k]; }, tid, a0, a1);
#pragma unroll
            for (int u = 0; u < 2; u++) {
                float a = u ? a1 : a0;
                int v = c*8 + js + u*4;
                int j = v & (H_ - 1);
                const float* ax = (v < H_) ? axr : axz;
                float s = sigmoidf_(a + ax[b*H_ + j]);
                ((v < H_) ? g_r0 : g_z0)[b*H_ + j] = s;
            }
        }
        gsync(&gen);

        // ---- Stage B: h~0 = tanh((h0*r0)@Wh.T + axh); h0' = h0 + z0*(h~0-h0) ----
        {
            float a0, dum;
            gemm_stage<4, H_>(wB, tile,
                [&](int bb, int k) { return h0p[bb*H_ + k] * g_r0[bb*H_ + k]; }, tid, a0, dum);
            int j = c*4 + js;
            float ht = tanhf(a0 + axh[b*H_ + j]);
            float z  = g_z0[b*H_ + j];
            float h  = h0p[b*H_ + j];
            h0n[b*H_ + j] = h + z * (ht - h);
        }
        gsync(&gen);

        // ---- Stage C: r1, z1 = sigmoid(cat(h1, h0') @ W.T + b) ----
        {
            float a0, a1;
            gemm_stage<8, 2*H_>(wC, tile,
                [&](int bb, int k) { return (k < H_) ? h1p[bb*H_ + k] : h0n[bb*H_ + k - H_]; },
                tid, a0, a1);
#pragma unroll
            for (int u = 0; u < 2; u++) {
                float a = u ? a1 : a0;
                int v = c*8 + js + u*4;
                int j = v & (H_ - 1);
                float bias = (v < H_) ? b_r1[j] : b_z1[j];
                float s = sigmoidf_(a + bias);
                ((v < H_) ? g_r1 : g_z1)[b*H_ + j] = s;
            }
        }
        gsync(&gen);

        // ---- Stage D: h~1 = tanh(cat(h1*r1, h0')@W.T + b); h1' = h1 + z1*(h~1-h1) ----
        {
            float a0, dum;
            gemm_stage<4, 2*H_>(wD, tile,
                [&](int bb, int k) {
                    return (k < H_) ? h1p[bb*H_ + k] * g_r1[bb*H_ + k] : h0n[bb*H_ + k - H_];
                }, tid, a0, dum);
            int j = c*4 + js;
            float ht = tanhf(a0 + b_h1[j]);
            float z  = g_z1[b*H_ + j];
            float h  = h1p[b*H_ + j];
            float hn = h + z * (ht - h);
            h1n[b*H_ + j] = hn;
            g_H1[(t*B_ + b)*H_ + j] = hn;
        }
        gsync(&gen);
    }

    // ---- final hidden state -> tail of d_out (after the logits region) ----
    if (out_size >= SB_*V_ + 2*B_*H_) {
        float* tail = d_out + (size_t)SB_ * V_;
        for (int idx = c*256 + tid; idx < B_*H_; idx += NB*256) {
            tail[idx]           = g_h0[0][idx];   // after 128 (even) steps, state is in buffer 0
            tail[B_*H_ + idx]   = g_h1[0][idx];
        }
    }
}

// ============================================================================
// Phase 3: logits = H1 @ Wy.T + by.  M=8192, N=10000, K=512.
// 128x64 tile, 8x4 micro, K-chunk 32. FFMA2 inner loop:
//   A pairs taken along M directly from smem; B duplicated in smem so both
//   FFMA2 operands load as ready-made 64-bit pairs (no per-kk packing).
// ============================================================================
__global__ __launch_bounds__(256) void logits_kernel(
    const float* __restrict__ Wy, const float* __restrict__ by, float* __restrict__ out)
{
    __shared__ float As[32*132];      // [kk][m], stride 132
    __shared__ float Bs[32*136];      // [kk][2n] duplicated, stride 136
    int tid = threadIdx.x;
    int m0 = blockIdx.y * 128;
    int n0 = blockIdx.x * 64;
    int tx = tid & 15, ty = tid >> 4;   // tx -> n (4 cols), ty -> m (8 rows)
    const float* A = g_H1;

    u64 accp[4][4];                   // [ip][j] = pair (acc[2ip][j], acc[2ip+1][j])
#pragma unroll
    for (int i = 0; i < 4; i++)
#pragma unroll
        for (int j = 0; j < 4; j++) accp[i][j] = 0ull;

    for (int k0 = 0; k0 < H_; k0 += 32) {
        __syncthreads();
#pragma unroll
        for (int r = 0; r < 16; r++) {          // A tile 128x32
            int idx = tid + r * 256;
            int row = idx >> 5, kk = idx & 31;
            As[kk*132 + row] = A[(m0 + row)*H_ + k0 + kk];
        }
#pragma unroll
        for (int r = 0; r < 8; r++) {           // B tile 64x32, duplicated (guard V)
            int idx = tid + r * 256;
            int row = idx >> 5, kk = idx & 31;
            int v = n0 + row;
            float val = (v < V_) ? Wy[v*H_ + k0 + kk] : 0.f;
            *reinterpret_cast<float2*>(Bs + kk*136 + row*2) = make_float2(val, val);
        }
        __syncthreads();
#pragma unroll
        for (int kk = 0; kk < 32; kk++) {
            ulonglong2 a01 = *reinterpret_cast<const ulonglong2*>(As + kk*132 + ty*8);     // (m0,m1),(m2,m3)
            ulonglong2 a23 = *reinterpret_cast<const ulonglong2*>(As + kk*132 + ty*8 + 4); // (m4,m5),(m6,m7)
            ulonglong2 b01 = *reinterpret_cast<const ulonglong2*>(Bs + kk*136 + tx*8);     // (b0,b0),(b1,b1)
            ulonglong2 b23 = *reinterpret_cast<const ulonglong2*>(Bs + kk*136 + tx*8 + 4); // (b2,b2),(b3,b3)
            fma2(accp[0][0], a01.x, b01.x); fma2(accp[1][0], a01.y, b01.x);
            fma2(accp[2][0], a23.x, b01.x); fma2(accp[3][0], a23.y, b01.x);
            fma2(accp[0][1], a01.x, b01.y); fma2(accp[1][1], a01.y, b01.y);
            fma2(accp[2][1], a23.x, b01.y); fma2(accp[3][1], a23.y, b01.y);
            fma2(accp[0][2], a01.x, b23.x); fma2(accp[1][2], a01.y, b23.x);
            fma2(accp[2][2], a23.x, b23.x); fma2(accp[3][2], a23.y, b23.x);
            fma2(accp[0][3], a01.x, b23.y); fma2(accp[1][3], a01.y, b23.y);
            fma2(accp[2][3], a23.x, b23.y); fma2(accp[3][3], a23.y, b23.y);
        }
    }
#pragma unroll
    for (int ip = 0; ip < 4; ip++) {
#pragma unroll
        for (int j = 0; j < 4; j++) {
            float2 f = unpack2(accp[ip][j]);
            int v = n0 + tx*4 + j;
            if (v < V_) {
                float bv = by[v];
                out[(size_t)(m0 + ty*8 + 2*ip)     * V_ + v] = f.x + bv;
                out[(size_t)(m0 + ty*8 + 2*ip + 1) * V_ + v] = f.y + bv;
            }
        }
    }
}

// ============================================================================
// kernel_launch
// ============================================================================
extern "C" void kernel_launch(void* const* d_in, const int* in_sizes, int n_in,
                              void* d_out, int out_size)
{
    const int*   inputs = (const int*)  d_in[0];
    const float* hidden = (const float*)d_in[1];
    const float* emb    = (const float*)d_in[2];
    const float* W_r0   = (const float*)d_in[3];
    const float* b_r0   = (const float*)d_in[4];
    const float* W_z0   = (const float*)d_in[5];
    const float* b_z0   = (const float*)d_in[6];
    const float* W_h0   = (const float*)d_in[7];
    const float* b_h0   = (const float*)d_in[8];
    const float* W_r1   = (const float*)d_in[9];
    const float* b_r1   = (const float*)d_in[10];
    const float* W_z1   = (const float*)d_in[11];
    const float* b_z1   = (const float*)d_in[12];
    const float* W_h1   = (const float*)d_in[13];
    const float* b_h1   = (const float*)d_in[14];
    const float* Wy     = (const float*)d_in[15];
    const float* by     = (const float*)d_in[16];
    float* out = (float*)d_out;

    cudaFuncSetAttribute(scan_kernel, cudaFuncAttributeMaxDynamicSharedMemorySize,
                         SCAN_SMEM_BYTES);

    // 1) reset grid-barrier flags (replay-safe)
    reset_kernel<<<1, NB>>>();
    // 2) precompute layer-0 x contributions (gather + 3 GEMMs)
    phase1_kernel<<<dim3(8, 128, 3), 256>>>(inputs, emb, W_r0, b_r0, W_z0, b_z0, W_h0, b_h0);
    // 3) persistent recurrent scan
    scan_kernel<<<NB, 256, SCAN_SMEM_BYTES>>>(hidden,
        W_r0, W_z0, W_h0, W_r1, b_r1, W_z1, b_z1, W_h1, b_h1, out, out_size);
    // 4) batched logits GEMM
    logits_kernel<<<dim3((V_ + 63) / 64, SB_ / 128), 256>>>(Wy, by, out);
}

// round 5
// speedup vs baseline: 1.3236x; 1.3236x over previous
#include <cuda_runtime.h>
#include <cuda_bf16.h>
#include <math.h>

#define S_ 128
#define B_ 64
#define V_ 10000
#define E_ 256
#define H_ 512
#define SB_ (S_*B_)     // 8192
#define NB 128          // persistent CTAs in scan kernel

typedef unsigned long long u64;

// ---------------- packed f32x2 helpers (Blackwell FFMA2) ----------------
__device__ __forceinline__ void fma2(u64& d, u64 a, u64 b) {
    asm("fma.rn.f32x2 %0, %1, %2, %0;" : "+l"(d) : "l"(a), "l"(b));
}
__device__ __forceinline__ float2 unpack2(u64 v) {
    float2 f;
    asm("mov.b64 {%0, %1}, %2;" : "=f"(f.x), "=f"(f.y) : "l"(v));
    return f;
}
__device__ __forceinline__ u64 pack_dup(float x) {
    u64 v;
    asm("mov.b64 %0, {%1, %1};" : "=l"(v) : "f"(x));
    return v;
}

// ---------------- device scratch ----------------
__device__ float g_ax[3][SB_*H_];     // layer0 x-contrib + bias, gates r,z,h (48 MB)
__device__ float g_H1[SB_*H_];        // h1 for every step (16 MB)
__device__ float g_h0[2][B_*H_];      // ping-pong layer0 state
__device__ float g_h1[2][B_*H_];      // ping-pong layer1 state
__device__ float g_r0[B_*H_], g_z0[B_*H_], g_r1[B_*H_], g_z1[B_*H_];
__device__ unsigned g_flag[NB*32];    // one 128B line per CTA flag

__global__ void reset_kernel() {
    for (int i = threadIdx.x; i < NB*32; i += blockDim.x) g_flag[i] = 0;
}

// Flag-array grid barrier. Each CTA's flag lives on its own 128B line (no
// sector sharing between release stores and other CTAs' flags). Only warp 0
// polls (32 pollers/CTA, 4 flags per lane) with nanosleep backoff -> poll
// traffic ~128x lower than all-thread polling. Visibility for non-polling
// threads: release(gpu) -> acquire(gpu, warp 0) -> bar.sync(cta) -> loads
// (PTX causality through the CTA barrier). Flags reset in stream order each
// launch, so graph replays are safe. All NB=128 CTAs are co-resident
// (91KB smem -> 1 CTA/SM, single wave on a 148-SM chip) so no deadlock.
__device__ __forceinline__ void gsync(unsigned* gen) {
    (*gen)++;
    unsigned g = *gen;
    __syncthreads();
    if (threadIdx.x == 0) {
        asm volatile("st.release.gpu.global.u32 [%0], %1;"
                     :: "l"(&g_flag[blockIdx.x*32]), "r"(g) : "memory");
    }
    if (threadIdx.x < 32) {
        for (int f = threadIdx.x; f < NB; f += 32) {
            unsigned v;
            while (true) {
                asm volatile("ld.acquire.gpu.global.u32 %0, [%1];"
                             : "=r"(v) : "l"(&g_flag[f*32]) : "memory");
                if (v >= g) break;
                __nanosleep(40);
            }
        }
    }
    __syncthreads();
}

__device__ __forceinline__ float sigmoidf_(float x) { return 1.f / (1.f + expf(-x)); }

// ============================================================================
// Phase 1: ax_g[t,b,:] = emb[tok[t,b]] @ Wx_g.T + b_g   (g = r,z,h of layer 0)
// M=8192, N=512, K=256. 64x64 tile, 4x4 micro, K-chunk 32.
// ============================================================================
__global__ __launch_bounds__(256) void phase1_kernel(
    const int*   __restrict__ inputs, const float* __restrict__ emb,
    const float* __restrict__ W_r0, const float* __restrict__ b_r0,
    const float* __restrict__ W_z0, const float* __restrict__ b_z0,
    const float* __restrict__ W_h0, const float* __restrict__ b_h0)
{
    __shared__ float As[32*68];
    __shared__ float Bs[32*68];
    __shared__ int   tok[64];
    int tid = threadIdx.x;
    int g = blockIdx.z;
    const float* W  = (g == 0) ? W_r0 : (g == 1) ? W_z0 : W_h0;
    const float* bg = (g == 0) ? b_r0 : (g == 1) ? b_z0 : b_h0;
    int m0 = blockIdx.y * 64;
    int n0 = blockIdx.x * 64;
    if (tid < 64) tok[tid] = inputs[m0 + tid];
    __syncthreads();

    int tx = tid & 15, ty = tid >> 4;
    float acc[4][4];
#pragma unroll
    for (int i = 0; i < 4; i++)
#pragma unroll
        for (int j = 0; j < 4; j++) acc[i][j] = 0.f;

    for (int k0 = 0; k0 < E_; k0 += 32) {
        __syncthreads();
#pragma unroll
        for (int r = 0; r < 8; r++) {
            int idx = tid + r * 256;
            int row = idx >> 5, kk = idx & 31;
            As[kk*68 + row] = emb[tok[row] * E_ + k0 + kk];
            Bs[kk*68 + row] = W[(n0 + row) * (H_ + E_) + H_ + k0 + kk];
        }
        __syncthreads();
#pragma unroll
        for (int kk = 0; kk < 32; kk++) {
            float4 a = *reinterpret_cast<const float4*>(As + kk*68 + ty*4);
            float4 b = *reinterpret_cast<const float4*>(Bs + kk*68 + tx*4);
            acc[0][0] += a.x*b.x; acc[0][1] += a.x*b.y; acc[0][2] += a.x*b.z; acc[0][3] += a.x*b.w;
            acc[1][0] += a.y*b.x; acc[1][1] += a.y*b.y; acc[1][2] += a.y*b.z; acc[1][3] += a.y*b.w;
            acc[2][0] += a.z*b.x; acc[2][1] += a.z*b.y; acc[2][2] += a.z*b.z; acc[2][3] += a.z*b.w;
            acc[3][0] += a.w*b.x; acc[3][1] += a.w*b.y; acc[3][2] += a.w*b.z; acc[3][3] += a.w*b.w;
        }
    }
    float* outp = g_ax[g];
#pragma unroll
    for (int i = 0; i < 4; i++) {
        int m = m0 + ty*4 + i;
#pragma unroll
        for (int j = 0; j < 4; j++) {
            int n = n0 + tx*4 + j;
            outp[m * H_ + n] = acc[i][j] + bg[n];
        }
    }
}

// ============================================================================
// Phase 2: persistent scan kernel. 128 CTAs x 256 threads, weight-stationary
// in smem (~72 KB/CTA). 4 GEMM stages/step with grid barriers. FFMA2 core.
// ============================================================================
constexpr int W_A = 8 * 512;
constexpr int W_B = 4 * 512;
constexpr int W_C = 8 * 1024;
constexpr int W_D = 4 * 1024;
constexpr int TILE_F = 64 * 68;
constexpr int SCAN_SMEM_BYTES = (W_A + W_B + W_C + W_D + TILE_F) * 4;  // 91136

template<int NCOLS, int K, class LoadF>
__device__ __forceinline__ void gemm_stage(const float* __restrict__ w, float* tile,
                                           LoadF load, int tid, float& acc0, float& acc1)
{
    int b = tid & 63, js = tid >> 6;
    u64 p0 = 0ull, p1 = 0ull;
    for (int k0 = 0; k0 < K; k0 += 64) {
        __syncthreads();
#pragma unroll
        for (int r = 0; r < 16; r++) {
            int idx = tid + r * 256;
            int bb = idx >> 6, kk = idx & 63;
            tile[bb*68 + kk] = load(bb, k0 + kk);
        }
        __syncthreads();
        const ulonglong2* a2  = reinterpret_cast<const ulonglong2*>(tile + b*68);
        const ulonglong2* w0p = reinterpret_cast<const ulonglong2*>(w + js*K + k0);
        const ulonglong2* w1p = reinterpret_cast<const ulonglong2*>(w + (js+4)*K + k0);
#pragma unroll
        for (int q = 0; q < 16; q++) {
            ulonglong2 a = a2[q];
            ulonglong2 x = w0p[q];
            fma2(p0, a.x, x.x);
            fma2(p0, a.y, x.y);
            if (NCOLS == 8) {
                ulonglong2 y = w1p[q];
                fma2(p1, a.x, y.x);
                fma2(p1, a.y, y.y);
            }
        }
    }
    float2 f0 = unpack2(p0);
    acc0 = f0.x + f0.y;
    if (NCOLS == 8) {
        float2 f1 = unpack2(p1);
        acc1 = f1.x + f1.y;
    } else {
        acc1 = 0.f;
    }
}

__global__ __launch_bounds__(256, 1) void scan_kernel(
    const float* __restrict__ hidden_in,
    const float* __restrict__ W_r0, const float* __restrict__ W_z0, const float* __restrict__ W_h0,
    const float* __restrict__ W_r1, const float* __restrict__ b_r1,
    const float* __restrict__ W_z1, const float* __restrict__ b_z1,
    const float* __restrict__ W_h1, const float* __restrict__ b_h1,
    float* __restrict__ d_out, int out_size)
{
    extern __shared__ float smem[];
    float* wA   = smem;
    float* wB   = wA + W_A;
    float* wC   = wB + W_B;
    float* wD   = wC + W_C;
    float* tile = wD + W_D;
    int tid = threadIdx.x;
    int c = blockIdx.x;

    for (int idx = tid; idx < W_A; idx += 256) {
        int i = idx >> 9, k = idx & 511;
        int v = c*8 + i;
        wA[idx] = (v < H_) ? W_r0[v*(H_+E_) + k] : W_z0[(v-H_)*(H_+E_) + k];
    }
    for (int idx = tid; idx < W_B; idx += 256) {
        int i = idx >> 9, k = idx & 511;
        wB[idx] = W_h0[(c*4 + i)*(H_+E_) + k];
    }
    for (int idx = tid; idx < W_C; idx += 256) {
        int i = idx >> 10, k = idx & 1023;
        int v = c*8 + i;
        wC[idx] = (v < H_) ? W_r1[v*(2*H_) + k] : W_z1[(v-H_)*(2*H_) + k];
    }
    for (int idx = tid; idx < W_D; idx += 256) {
        int i = idx >> 10, k = idx & 1023;
        wD[idx] = W_h1[(c*4 + i)*(2*H_) + k];
    }
    for (int idx = c*256 + tid; idx < B_*H_; idx += NB*256) {
        g_h0[0][idx] = hidden_in[idx];
        g_h1[0][idx] = hidden_in[B_*H_ + idx];
    }
    unsigned gen = 0;
    gsync(&gen);

    int b = tid & 63, js = tid >> 6;

    for (int t = 0; t < S_; t++) {
        int p = t & 1;
        const float* h0p = g_h0[p];
        const float* h1p = g_h1[p];
        float* h0n = g_h0[p ^ 1];
        float* h1n = g_h1[p ^ 1];
        const float* axr = g_ax[0] + t * (B_*H_);
        const float* axz = g_ax[1] + t * (B_*H_);
        const float* axh = g_ax[2] + t * (B_*H_);

        {   // Stage A: r0, z0
            float a0, a1;
            gemm_stage<8, H_>(wA, tile,
                [&](int bb, int k) { return h0p[bb*H_ + k]; }, tid, a0, a1);
#pragma unroll
            for (int u = 0; u < 2; u++) {
                float a = u ? a1 : a0;
                int v = c*8 + js + u*4;
                int j = v & (H_ - 1);
                const float* ax = (v < H_) ? axr : axz;
                float s = sigmoidf_(a + ax[b*H_ + j]);
                ((v < H_) ? g_r0 : g_z0)[b*H_ + j] = s;
            }
        }
        gsync(&gen);

        {   // Stage B: h~0, h0'
            float a0, dum;
            gemm_stage<4, H_>(wB, tile,
                [&](int bb, int k) { return h0p[bb*H_ + k] * g_r0[bb*H_ + k]; }, tid, a0, dum);
            int j = c*4 + js;
            float ht = tanhf(a0 + axh[b*H_ + j]);
            float z  = g_z0[b*H_ + j];
            float h  = h0p[b*H_ + j];
            h0n[b*H_ + j] = h + z * (ht - h);
        }
        gsync(&gen);

        {   // Stage C: r1, z1
            float a0, a1;
            gemm_stage<8, 2*H_>(wC, tile,
                [&](int bb, int k) { return (k < H_) ? h1p[bb*H_ + k] : h0n[bb*H_ + k - H_]; },
                tid, a0, a1);
#pragma unroll
            for (int u = 0; u < 2; u++) {
                float a = u ? a1 : a0;
                int v = c*8 + js + u*4;
                int j = v & (H_ - 1);
                float bias = (v < H_) ? b_r1[j] : b_z1[j];
                float s = sigmoidf_(a + bias);
                ((v < H_) ? g_r1 : g_z1)[b*H_ + j] = s;
            }
        }
        gsync(&gen);

        {   // Stage D: h~1, h1'
            float a0, dum;
            gemm_stage<4, 2*H_>(wD, tile,
                [&](int bb, int k) {
                    return (k < H_) ? h1p[bb*H_ + k] * g_r1[bb*H_ + k] : h0n[bb*H_ + k - H_];
                }, tid, a0, dum);
            int j = c*4 + js;
            float ht = tanhf(a0 + b_h1[j]);
            float z  = g_z1[b*H_ + j];
            float h  = h1p[b*H_ + j];
            float hn = h + z * (ht - h);
            h1n[b*H_ + j] = hn;
            g_H1[(t*B_ + b)*H_ + j] = hn;
        }
        gsync(&gen);
    }

    if (out_size >= SB_*V_ + 2*B_*H_) {
        float* tail = d_out + (size_t)SB_ * V_;
        for (int idx = c*256 + tid; idx < B_*H_; idx += NB*256) {
            tail[idx]           = g_h0[0][idx];   // after 128 (even) steps -> buffer 0
            tail[B_*H_ + idx]   = g_h1[0][idx];
        }
    }
}

// ============================================================================
// Phase 3: logits = H1 @ Wy.T + by.  M=8192, N=10000, K=512.
// CTA tile 256(M) x 128(N), K-chunk 16. Per thread: Mr=16, Nr=8 -> 64 FFMA2/kk
// against 96 B LDS -> FMA-bound (256 vs <=192 cyc per SM per kk).
//
// Lane mapping: lm = lane&3 (4 m-groups/warp), ln = lane>>2 (8 n-groups/warp);
// warp_m = warp&3, warp_n = warp>>2. g = warp_m*4+lm in 0..15 (16 m per group),
// ng = warp_n*8+ln in 0..15 (8 n per group).
//
// Interleaved smem layouts (conflict-free per LDS.128):
//  A: m_global = g*16 + s*4 + e  -> addr = kk*264 + s*64 + g*4 + e
//     per instruction (s fixed): 4 distinct 16B segs, 16B apart, x8 broadcast.
//  B: n_global = ng*8 + s2*4 + e -> addr = kk*136 + s2*64 + ng*4 + e
//     per instruction (s2 fixed): 8 distinct 16B segs, 16B apart, x4 broadcast.
// ============================================================================
constexpr int ASTR = 264;   // floats per kk row of As (256 + 8 pad)
constexpr int BSTR = 136;   // floats per kk row of Bs (128 + 8 pad)

__global__ __launch_bounds__(256, 1) void logits_kernel(
    const float* __restrict__ Wy, const float* __restrict__ by, float* __restrict__ out)
{
    __shared__ float As[16*ASTR];
    __shared__ float Bs[16*BSTR];
    int tid  = threadIdx.x;
    int lane = tid & 31, warp = tid >> 5;
    int lm = lane & 3, ln = lane >> 2;
    int warp_m = warp & 3, warp_n = warp >> 2;
    int g  = warp_m*4 + lm;    // 0..15
    int ng = warp_n*8 + ln;    // 0..15
    int m0 = blockIdx.y * 256;
    int n0 = blockIdx.x * 128;
    const float* A = g_H1;

    u64 acc[8][8];             // [q = s*2+h][n]; pair = (m, m+1), m = g*16+s*4+h*2
#pragma unroll
    for (int q = 0; q < 8; q++)
#pragma unroll
        for (int n = 0; n < 8; n++) acc[q][n] = 0ull;

    for (int k0 = 0; k0 < H_; k0 += 16) {
        __syncthreads();
        // ---- A tile: 256 rows x 16 k as float4 global loads, scattered STS.32
#pragma unroll
        for (int i = 0; i < 4; i++) {
            int fidx = tid + i * 256;          // 0..1023
            int m = fidx >> 2, j = fidx & 3;   // m 0..255, j float4 index
            float4 vA = *reinterpret_cast<const float4*>(A + (size_t)(m0 + m)*H_ + k0 + j*4);
            int s = (m >> 2) & 3, gg = m >> 4, e = m & 3;
            int base = s*64 + gg*4 + e;
            As[(j*4 + 0)*ASTR + base] = vA.x;
            As[(j*4 + 1)*ASTR + base] = vA.y;
            As[(j*4 + 2)*ASTR + base] = vA.z;
            As[(j*4 + 3)*ASTR + base] = vA.w;
        }
        // ---- B tile: 128 rows x 16 k (guard V), scattered STS.32
#pragma unroll
        for (int i = 0; i < 2; i++) {
            int fidx = tid + i * 256;          // 0..511
            int row = fidx >> 2, j = fidx & 3;
            int v = n0 + row;
            float4 vB = make_float4(0.f, 0.f, 0.f, 0.f);
            if (v < V_) vB = *reinterpret_cast<const float4*>(Wy + (size_t)v*H_ + k0 + j*4);
            int s2 = (row >> 2) & 1, nn = row >> 3, e = row & 3;
            int base = s2*64 + nn*4 + e;
            Bs[(j*4 + 0)*BSTR + base] = vB.x;
            Bs[(j*4 + 1)*BSTR + base] = vB.y;
            Bs[(j*4 + 2)*BSTR + base] = vB.z;
            Bs[(j*4 + 3)*BSTR + base] = vB.w;
        }
        __syncthreads();
#pragma unroll
        for (int kk = 0; kk < 16; kk++) {
            const float* ar = As + kk*ASTR;
            const float* br = Bs + kk*BSTR;
            ulonglong2 a[4];
#pragma unroll
            for (int s = 0; s < 4; s++)
                a[s] = *reinterpret_cast<const ulonglong2*>(ar + s*64 + g*4);
            float4 b0 = *reinterpret_cast<const float4*>(br + ng*4);
            float4 b1 = *reinterpret_cast<const float4*>(br + 64 + ng*4);
            u64 bd[8];
            bd[0] = pack_dup(b0.x); bd[1] = pack_dup(b0.y);
            bd[2] = pack_dup(b0.z); bd[3] = pack_dup(b0.w);
            bd[4] = pack_dup(b1.x); bd[5] = pack_dup(b1.y);
            bd[6] = pack_dup(b1.z); bd[7] = pack_dup(b1.w);
#pragma unroll
            for (int s = 0; s < 4; s++) {
#pragma unroll
                for (int n = 0; n < 8; n++) {
                    fma2(acc[s*2 + 0][n], a[s].x, bd[n]);
                    fma2(acc[s*2 + 1][n], a[s].y, bd[n]);
                }
            }
        }
    }
    // ---- epilogue: m = m0 + g*16 + s*4 + h*2 + {0,1}; v = n0 + ng*8 + n
#pragma unroll
    for (int s = 0; s < 4; s++) {
#pragma unroll
        for (int h = 0; h < 2; h++) {
            int m = m0 + g*16 + s*4 + h*2;
            float* r0 = out + (size_t)m * V_;
            float* r1 = out + (size_t)(m + 1) * V_;
#pragma unroll
            for (int n = 0; n < 8; n++) {
                int v = n0 + ng*8 + n;
                if (v < V_) {
                    float2 f = unpack2(acc[s*2 + h][n]);
                    float bv = by[v];
                    r0[v] = f.x + bv;
                    r1[v] = f.y + bv;
                }
            }
        }
    }
}

// ============================================================================
// kernel_launch
// ============================================================================
extern "C" void kernel_launch(void* const* d_in, const int* in_sizes, int n_in,
                              void* d_out, int out_size)
{
    const int*   inputs = (const int*)  d_in[0];
    const float* hidden = (const float*)d_in[1];
    const float* emb    = (const float*)d_in[2];
    const float* W_r0   = (const float*)d_in[3];
    const float* b_r0   = (const float*)d_in[4];
    const float* W_z0   = (const float*)d_in[5];
    const float* b_z0   = (const float*)d_in[6];
    const float* W_h0   = (const float*)d_in[7];
    const float* b_h0   = (const float*)d_in[8];
    const float* W_r1   = (const float*)d_in[9];
    const float* b_r1   = (const float*)d_in[10];
    const float* W_z1   = (const float*)d_in[11];
    const float* b_z1   = (const float*)d_in[12];
    const float* W_h1   = (const float*)d_in[13];
    const float* b_h1   = (const float*)d_in[14];
    const float* Wy     = (const float*)d_in[15];
    const float* by     = (const float*)d_in[16];
    float* out = (float*)d_out;

    cudaFuncSetAttribute(scan_kernel, cudaFuncAttributeMaxDynamicSharedMemorySize,
                         SCAN_SMEM_BYTES);

    reset_kernel<<<1, 256>>>();
    phase1_kernel<<<dim3(8, 128, 3), 256>>>(inputs, emb, W_r0, b_r0, W_z0, b_z0, W_h0, b_h0);
    scan_kernel<<<NB, 256, SCAN_SMEM_BYTES>>>(hidden,
        W_r0, W_z0, W_h0, W_r1, b_r1, W_z1, b_z1, W_h1, b_h1, out, out_size);
    logits_kernel<<<dim3((V_ + 127) / 128, SB_ / 256), 256>>>(Wy, by, out);
}